// round 1
// baseline (speedup 1.0000x reference)
#include <cuda_runtime.h>
#include <math.h>

#define D_TOT 2304
#define OUTC  512
#define INC   256
#define HH    56
#define WW    56
#define HWX   3136          // 56*56
#define NIMG  16
#define NPIX  (NIMG*HWX)    // 50176

// scratch (device globals: no allocation allowed)
__device__ int   g_kidx[OUTC];
__device__ float g_maxrow[D_TOT];
__device__ float g_mul[OUTC];
__device__ int   g_sel[OUTC];
__device__ int   g_active;

// ---------------------------------------------------------------------------
// Kernel A: ALSH hash per kernel row.
// h = floor( a[:D].w + sum_i a[D+i] * (||w||^2)^(2^i) ), idx = mod(h,16) in [0,16)
// ---------------------------------------------------------------------------
__global__ void __launch_bounds__(256) hash_kernels(const float* __restrict__ W,
                                                    const float* __restrict__ a) {
    const int o   = blockIdx.x;
    const int tid = threadIdx.x;
    const float* w = W + (size_t)o * D_TOT;
    float dot = 0.f, n2 = 0.f;
    for (int i = tid; i < D_TOT; i += 256) {
        float v = w[i];
        dot += a[i] * v;
        n2  += v * v;
    }
    __shared__ float s1[256], s2[256];
    s1[tid] = dot; s2[tid] = n2;
    __syncthreads();
    for (int st = 128; st > 0; st >>= 1) {
        if (tid < st) { s1[tid] += s1[tid+st]; s2[tid] += s2[tid+st]; }
        __syncthreads();
    }
    if (tid == 0) {
        float acc = s1[0];
        float pw  = s2[0];          // n2^1
        acc += a[D_TOT+0] * pw; pw *= pw;   // -> n2^2
        acc += a[D_TOT+1] * pw; pw *= pw;   // -> n2^4
        acc += a[D_TOT+2] * pw; pw *= pw;   // -> n2^8
        acc += a[D_TOT+3] * pw; pw *= pw;   // -> n2^16
        acc += a[D_TOT+4] * pw;
        float h = floorf(acc);
        float r = fmodf(h, 16.f);
        if (r < 0.f) r += 16.f;
        g_kidx[o] = (int)r;
    }
}

// ---------------------------------------------------------------------------
// Kernel B: per-row max of the im2col matrix.
// Row (kh,kw,c): max over x[n,c,r,s] with r in R(kh), s in S(kw); non-center
// taps also see padding zeros -> fmax with 0.
// ---------------------------------------------------------------------------
__global__ void __launch_bounds__(256) max_rows(const float* __restrict__ x) {
    const int c   = blockIdx.x;
    const int tid = threadIdx.x;
    float m[9];
#pragma unroll
    for (int i = 0; i < 9; i++) m[i] = -1e30f;

    for (int t = tid; t < NIMG * HWX; t += 256) {
        int n = t / HWX;
        int i = t - n * HWX;
        int r = i / WW;
        int s = i - r * WW;
        float v = __ldg(&x[((size_t)n * INC + c) * HWX + i]);
        bool r0 = (r <= 54), r2 = (r >= 1), c0 = (s <= 54), c2 = (s >= 1);
        m[4] = fmaxf(m[4], v);
        if (r0) {
            m[1] = fmaxf(m[1], v);
            if (c0) m[0] = fmaxf(m[0], v);
            if (c2) m[2] = fmaxf(m[2], v);
        }
        if (c0) m[3] = fmaxf(m[3], v);
        if (c2) m[5] = fmaxf(m[5], v);
        if (r2) {
            m[7] = fmaxf(m[7], v);
            if (c0) m[6] = fmaxf(m[6], v);
            if (c2) m[8] = fmaxf(m[8], v);
        }
    }
    __shared__ float sred[256];
    for (int q = 0; q < 9; q++) {
        sred[tid] = m[q];
        __syncthreads();
        for (int st = 128; st > 0; st >>= 1) {
            if (tid < st) sred[tid] = fmaxf(sred[tid], sred[tid+st]);
            __syncthreads();
        }
        if (tid == 0) {
            float mv = sred[0];
            if (q != 4) mv = fmaxf(mv, 0.f);   // padding zeros for off-center taps
            g_maxrow[q * INC + c] = mv;
        }
        __syncthreads();
    }
}

// ---------------------------------------------------------------------------
// Kernel C: query hash + routing table (mask, count, compacted list, scale).
// ---------------------------------------------------------------------------
__global__ void __launch_bounds__(512) build_route(const float* __restrict__ a) {
    const int tid = threadIdx.x;
    __shared__ float red[512];

    float ss = 0.f;
    for (int i = tid; i < D_TOT; i += 512) { float v = g_maxrow[i]; ss += v * v; }
    red[tid] = ss; __syncthreads();
    for (int st = 256; st > 0; st >>= 1) {
        if (tid < st) red[tid] += red[tid+st];
        __syncthreads();
    }
    __shared__ float s_norm;
    if (tid == 0) s_norm = sqrtf(red[0]);
    __syncthreads();

    float dot = 0.f;
    for (int i = tid; i < D_TOT; i += 512) dot += a[i] * g_maxrow[i];
    red[tid] = dot; __syncthreads();
    for (int st = 256; st > 0; st >>= 1) {
        if (tid < st) red[tid] += red[tid+st];
        __syncthreads();
    }

    __shared__ int s_q, s_cnt, s_pos;
    if (tid == 0) {
        float hs = 0.5f * (a[D_TOT] + a[D_TOT+1] + a[D_TOT+2] + a[D_TOT+3] + a[D_TOT+4]);
        float acc = red[0] / s_norm + hs;
        float h = floorf(acc);
        float r = fmodf(h, 16.f);
        if (r < 0.f) r += 16.f;
        s_q = (int)r;
        s_cnt = 0; s_pos = 0;
    }
    __syncthreads();

    int match = (g_kidx[tid] == s_q) ? 1 : 0;
    if (match) atomicAdd(&s_cnt, 1);
    __syncthreads();
    int count = s_cnt;

    if (count > 0) {
        g_mul[tid] = match ? ((float)OUTC / (float)count) : 0.f;
        if (match) { int pp = atomicAdd(&s_pos, 1); g_sel[pp] = tid; }
        if (tid == 0) g_active = count;
    } else {
        g_mul[tid] = 1.f;
        g_sel[tid] = tid;
        if (tid == 0) g_active = OUTC;
    }
}

// ---------------------------------------------------------------------------
// Kernel D: bias broadcast into all outputs (float4).
// out[n,o,h,w] layout -> float4 index i: (n*512+o) = i/784
// ---------------------------------------------------------------------------
__global__ void __launch_bounds__(256) fill_bias(float4* __restrict__ out,
                                                 const float* __restrict__ bias) {
    int i = blockIdx.x * 256 + threadIdx.x;   // < 6,422,528
    int chimg = i / 784;
    int o = chimg & 511;
    float b = __ldg(&bias[o]);
    out[i] = make_float4(b, b, b, b);
}

// ---------------------------------------------------------------------------
// Kernel E: implicit-GEMM conv over the compacted channel list.
// C[g, p] = sum_d W[g,d] * patch[d,p], out = mul[g]*C + bias[g]
// BM=32 (channels), BN=128 (pixels), BK=16, 256 threads, 4x4 per thread.
// ---------------------------------------------------------------------------
__global__ void __launch_bounds__(256) conv_gemm(const float* __restrict__ x,
                                                 const float* __restrict__ W,
                                                 const float* __restrict__ bias,
                                                 float* __restrict__ out) {
    const int active = g_active;
    const int mt = blockIdx.y;
    if (mt * 32 >= active) return;           // routed-out channel tiles exit
    const int nt  = blockIdx.x;
    const int tid = threadIdx.x;

    __shared__ float Ws[16][36];             // [kk][channel], padded
    __shared__ float Ps[16][132];            // [kk][pixel], padded
    __shared__ int   selS[32];
    __shared__ float mulS[32];

    if (tid < 32) {
        int gi = mt * 32 + tid;
        int g  = (gi < active) ? g_sel[gi] : -1;
        selS[tid] = g;
        mulS[tid] = (g >= 0) ? g_mul[g] : 0.f;
    }

    // P-tile load mapping: fixed (j, kk_base) per thread
    const int j   = tid & 127;
    const int kkb = tid >> 7;                // 0 or 1
    const int p   = nt * 128 + j;
    const int pn  = p / HWX;
    const int prem = p - pn * HWX;
    const int py  = prem / WW;
    const int px  = prem - py * WW;
    const float* xb = x + (size_t)pn * INC * HWX;

    // W-tile load mapping: 2 elems per thread
    const int wkk = tid & 15;
    const int wi  = tid >> 4;                // 0..15 (second elem at wi+16)

    const int tm = tid >> 5;                 // 0..7  (channel quad)
    const int tn = tid & 31;                 // 0..31 (pixel quad)

    float acc[4][4];
#pragma unroll
    for (int u = 0; u < 4; u++)
#pragma unroll
        for (int v = 0; v < 4; v++) acc[u][v] = 0.f;

    __syncthreads();                         // selS visible

    for (int k0 = 0; k0 < D_TOT; k0 += 16) {
        // --- load W tile (gathered rows via compacted list) ---
        {
            int g0 = selS[wi];
            int g1 = selS[wi + 16];
            float v0 = (g0 >= 0) ? __ldg(&W[(size_t)g0 * D_TOT + k0 + wkk]) : 0.f;
            float v1 = (g1 >= 0) ? __ldg(&W[(size_t)g1 * D_TOT + k0 + wkk]) : 0.f;
            Ws[wkk][wi]      = v0;
            Ws[wkk][wi + 16] = v1;
        }
        // --- load P tile (implicit im2col) ---
#pragma unroll
        for (int q = 0; q < 8; q++) {
            int kk = kkb + 2 * q;
            int d  = k0 + kk;
            int c  = d & 255;
            int t9 = d >> 8;                 // (kh*3+kw) in [0,9)
            int kh = (t9 * 11) >> 5;         // t9/3
            int kw = t9 - 3 * kh;
            int r  = py + kh - 1;
            int s  = px + kw - 1;
            float v = 0.f;
            if ((unsigned)r < 56u && (unsigned)s < 56u)
                v = __ldg(&xb[c * HWX + r * WW + s]);
            Ps[kk][j] = v;
        }
        __syncthreads();
        // --- compute ---
#pragma unroll
        for (int kk = 0; kk < 16; kk++) {
            float4 wv = *(const float4*)&Ws[kk][tm * 4];
            float4 pv = *(const float4*)&Ps[kk][tn * 4];
            acc[0][0] += wv.x * pv.x; acc[0][1] += wv.x * pv.y;
            acc[0][2] += wv.x * pv.z; acc[0][3] += wv.x * pv.w;
            acc[1][0] += wv.y * pv.x; acc[1][1] += wv.y * pv.y;
            acc[1][2] += wv.y * pv.z; acc[1][3] += wv.y * pv.w;
            acc[2][0] += wv.z * pv.x; acc[2][1] += wv.z * pv.y;
            acc[2][2] += wv.z * pv.z; acc[2][3] += wv.z * pv.w;
            acc[3][0] += wv.w * pv.x; acc[3][1] += wv.w * pv.y;
            acc[3][2] += wv.w * pv.z; acc[3][3] += wv.w * pv.w;
        }
        __syncthreads();
    }

    // --- epilogue: out = mul * acc + bias ---
    int pe_n[4], pe_i[4];
#pragma unroll
    for (int col = 0; col < 4; col++) {
        int pe = nt * 128 + tn * 4 + col;
        int ne = pe / HWX;
        pe_n[col] = ne;
        pe_i[col] = pe - ne * HWX;
    }
#pragma unroll
    for (int u = 0; u < 4; u++) {
        int g = selS[tm * 4 + u];
        if (g < 0) continue;
        float mu = mulS[tm * 4 + u];
        float b  = __ldg(&bias[g]);
#pragma unroll
        for (int col = 0; col < 4; col++) {
            out[((size_t)pe_n[col] * OUTC + g) * HWX + pe_i[col]] = mu * acc[u][col] + b;
        }
    }
}

// ---------------------------------------------------------------------------
extern "C" void kernel_launch(void* const* d_in, const int* in_sizes, int n_in,
                              void* d_out, int out_size) {
    const float* x = nullptr;
    const float* W = nullptr;
    const float* bias = nullptr;
    const float* a = nullptr;
    for (int i = 0; i < n_in; i++) {
        if (in_sizes[i] == NIMG * INC * HWX)      x    = (const float*)d_in[i];
        else if (in_sizes[i] == OUTC * D_TOT)     W    = (const float*)d_in[i];
        else if (in_sizes[i] == OUTC)             bias = (const float*)d_in[i];
        else if (in_sizes[i] == D_TOT + 5)        a    = (const float*)d_in[i];
    }
    float* out = (float*)d_out;

    hash_kernels<<<OUTC, 256>>>(W, a);
    max_rows<<<INC, 256>>>(x);
    build_route<<<1, 512>>>(a);
    fill_bias<<<(NPIX * (OUTC / 4)) / 256, 256>>>((float4*)out, bias);
    conv_gemm<<<dim3(NPIX / 128, OUTC / 32), 256>>>(x, W, bias, out);
}

// round 3
// speedup vs baseline: 4.5434x; 4.5434x over previous
#include <cuda_runtime.h>
#include <math.h>
#include <stdint.h>

#define D_TOT 2304
#define OUTC  512
#define INC   256
#define HWX   3136          // 56*56
#define NIMG  16
#define NPIX  (NIMG*HWX)    // 50176

#define BK    32
#define NITER (D_TOT/BK)    // 72
#define MT    128           // CTA M tile (channels)
#define NT    128           // CTA N tile (pixels)

// SMEM layout (uint32 units): fragment-ordered tf32 tiles, double buffered.
// A: [kstep(4) x 1032] : per kstep 8 mtiles * (32 lanes * 4 regs) = 1024 (+8 pad)
// B: [kstep(4) x 1056] : per kstep 16 ntiles * 66 (32 lanes * 2 regs + 2 pad)
#define A_KSTRIDE 1032
#define A_BUF     4128      // 4*1032
#define B_NSTRIDE 66
#define B_KSTRIDE 1056      // 16*66
#define B_BUF     4224      // 4*1056
#define B_OFF     8256      // 2*A_BUF
#define SMEM_U32  (B_OFF + 2*B_BUF)   // 16704 u32 = 66816 B

// scratch (device globals: no allocation allowed)
__device__ int   g_kidx[OUTC];
__device__ float g_maxrow[D_TOT];
__device__ float g_mul[OUTC];
__device__ int   g_sel[OUTC];
__device__ int   g_active;

// ============================ PTX helpers ====================================
__device__ __forceinline__ uint32_t f2tf(float f) {   // unbiased tf32 rounding
    uint32_t u; asm("cvt.rna.tf32.f32 %0, %1;" : "=r"(u) : "f"(f)); return u;
}
__device__ __forceinline__ void mma8(float* c, const uint32_t* a, const uint32_t* b) {
    asm volatile(
        "mma.sync.aligned.m16n8k8.row.col.f32.tf32.tf32.f32 "
        "{%0,%1,%2,%3}, {%4,%5,%6,%7}, {%8,%9}, {%0,%1,%2,%3};\n"
        : "+f"(c[0]), "+f"(c[1]), "+f"(c[2]), "+f"(c[3])
        : "r"(a[0]), "r"(a[1]), "r"(a[2]), "r"(a[3]), "r"(b[0]), "r"(b[1]));
}

// ============================ small kernels ==================================
__global__ void __launch_bounds__(256) hash_kernels(const float* __restrict__ W,
                                                    const float* __restrict__ a) {
    const int o   = blockIdx.x;
    const int tid = threadIdx.x;
    const float* w = W + (size_t)o * D_TOT;
    float dot = 0.f, n2 = 0.f;
    for (int i = tid; i < D_TOT; i += 256) {
        float v = w[i];
        dot += a[i] * v;
        n2  += v * v;
    }
    __shared__ float s1[256], s2[256];
    s1[tid] = dot; s2[tid] = n2;
    __syncthreads();
    for (int st = 128; st > 0; st >>= 1) {
        if (tid < st) { s1[tid] += s1[tid+st]; s2[tid] += s2[tid+st]; }
        __syncthreads();
    }
    if (tid == 0) {
        float acc = s1[0];
        float pw  = s2[0];
        acc += a[D_TOT+0] * pw; pw *= pw;
        acc += a[D_TOT+1] * pw; pw *= pw;
        acc += a[D_TOT+2] * pw; pw *= pw;
        acc += a[D_TOT+3] * pw; pw *= pw;
        acc += a[D_TOT+4] * pw;
        float h = floorf(acc);
        float r = fmodf(h, 16.f);
        if (r < 0.f) r += 16.f;
        g_kidx[o] = (int)r;
    }
}

__global__ void __launch_bounds__(256) max_rows(const float* __restrict__ x) {
    const int c   = blockIdx.x;
    const int tid = threadIdx.x;
    float m[9];
#pragma unroll
    for (int i = 0; i < 9; i++) m[i] = -1e30f;
    for (int t = tid; t < NIMG * HWX; t += 256) {
        int n = t / HWX;
        int i = t - n * HWX;
        int r = i / 56;
        int s = i - r * 56;
        float v = __ldg(&x[((size_t)n * INC + c) * HWX + i]);
        bool r0 = (r <= 54), r2 = (r >= 1), c0 = (s <= 54), c2 = (s >= 1);
        m[4] = fmaxf(m[4], v);
        if (r0) { m[1] = fmaxf(m[1], v); if (c0) m[0] = fmaxf(m[0], v); if (c2) m[2] = fmaxf(m[2], v); }
        if (c0) m[3] = fmaxf(m[3], v);
        if (c2) m[5] = fmaxf(m[5], v);
        if (r2) { m[7] = fmaxf(m[7], v); if (c0) m[6] = fmaxf(m[6], v); if (c2) m[8] = fmaxf(m[8], v); }
    }
    __shared__ float sred[256];
    for (int q = 0; q < 9; q++) {
        sred[tid] = m[q];
        __syncthreads();
        for (int st = 128; st > 0; st >>= 1) {
            if (tid < st) sred[tid] = fmaxf(sred[tid], sred[tid+st]);
            __syncthreads();
        }
        if (tid == 0) {
            float mv = sred[0];
            if (q != 4) mv = fmaxf(mv, 0.f);
            g_maxrow[q * INC + c] = mv;
        }
        __syncthreads();
    }
}

__global__ void __launch_bounds__(512) build_route(const float* __restrict__ a) {
    const int tid = threadIdx.x;
    __shared__ float red[512];

    float ss = 0.f;
    for (int i = tid; i < D_TOT; i += 512) { float v = g_maxrow[i]; ss += v * v; }
    red[tid] = ss; __syncthreads();
    for (int st = 256; st > 0; st >>= 1) { if (tid < st) red[tid] += red[tid+st]; __syncthreads(); }
    __shared__ float s_norm;
    if (tid == 0) s_norm = sqrtf(red[0]);
    __syncthreads();

    float dot = 0.f;
    for (int i = tid; i < D_TOT; i += 512) dot += a[i] * g_maxrow[i];
    red[tid] = dot; __syncthreads();
    for (int st = 256; st > 0; st >>= 1) { if (tid < st) red[tid] += red[tid+st]; __syncthreads(); }

    __shared__ int s_q, s_cnt, s_pos;
    if (tid == 0) {
        float hs = 0.5f * (a[D_TOT] + a[D_TOT+1] + a[D_TOT+2] + a[D_TOT+3] + a[D_TOT+4]);
        float acc = red[0] / s_norm + hs;
        float h = floorf(acc);
        float r = fmodf(h, 16.f);
        if (r < 0.f) r += 16.f;
        s_q = (int)r;
        s_cnt = 0; s_pos = 0;
    }
    __syncthreads();

    int match = (g_kidx[tid] == s_q) ? 1 : 0;
    if (match) atomicAdd(&s_cnt, 1);
    __syncthreads();
    int count = s_cnt;

    if (count > 0) {
        g_mul[tid] = match ? ((float)OUTC / (float)count) : 0.f;
        if (match) { int pp = atomicAdd(&s_pos, 1); g_sel[pp] = tid; }
        if (tid == 0) g_active = count;
    } else {
        g_mul[tid] = 1.f;
        g_sel[tid] = tid;
        if (tid == 0) g_active = OUTC;
    }
}

__global__ void __launch_bounds__(256) fill_bias(float4* __restrict__ out,
                                                 const float* __restrict__ bias) {
    if (g_active == OUTC) return;   // conv writes every channel in this case
    int i = blockIdx.x * 256 + threadIdx.x;
    int chimg = i / 784;
    int o = chimg & 511;
    float b = __ldg(&bias[o]);
    out[i] = make_float4(b, b, b, b);
}

// ============================ tensor-core conv ===============================
// D[m,n] = sum_k A[m,k]*B[n,k]; A row m -> W[g_sel[...]], B row n -> im2col col.
// mma.sync m16n8k8 tf32. 8 warps, warp tile 64x32 (wm in 0..1, wn in 0..3).
__global__ void __launch_bounds__(256) conv_mma(const float* __restrict__ x,
                                                const float* __restrict__ W,
                                                const float* __restrict__ bias,
                                                float* __restrict__ out) {
    const int active = g_active;
    const int mt = blockIdx.y;
    if (mt * MT >= active) return;
    const int nt  = blockIdx.x;
    const int tid = threadIdx.x;
    const int wid  = tid >> 5;
    const int lane = tid & 31;
    const int wm = wid & 1;             // 0..1  (64 rows)
    const int wn = wid >> 1;            // 0..3  (32 cols)

    extern __shared__ uint32_t sm[];

    // ---- A staging mapping: lane_k = k within chunk, rows rb+8i ----
    const int lane_k = tid & 31;
    const int rb     = tid >> 5;        // 0..7
    uint32_t aoff[16];
#pragma unroll
    for (int i = 0; i < 16; i++) {
        int gi = mt * MT + rb + 8 * i;
        int g  = (gi < active) ? g_sel[gi] : 0;
        aoff[i] = (uint32_t)g * D_TOT;
    }
    const int a_kstep = lane_k >> 3;
    const int a_col   = lane_k & 7;
    // frag pos: lane=(row&7)<<2 | (col&3); reg = (row>=8) | ((col>=4)<<1)
    const int a_base  = a_kstep * A_KSTRIDE + ((rb << 2) | (a_col & 3)) * 4
                      + ((a_col >> 2) << 1);

    // ---- B staging mapping: pixel np, k = kb + 2i ----
    const int np = tid & 127;
    const int kb = tid >> 7;            // 0/1
    const int p  = nt * NT + np;
    const int pn = p / HWX;
    const int prem = p - pn * HWX;
    const int py = prem / 56;
    const int px = prem - py * 56;
    const float* xb = x + (size_t)pn * INC * HWX;
    const int b_nt = np >> 3;
    const int b_nl = np & 7;

    float aR[16], bR[16];

    // ---------------- prologue: stage chunk 0 into buf 0 ----------------
    {
        const int k0 = 0;
#pragma unroll
        for (int i = 0; i < 16; i++) aR[i] = __ldg(&W[aoff[i] + k0 + lane_k]);
        const int r = py - 1, s = px - 1;      // tap (0,0) for k0=0
        const bool ok = ((unsigned)r < 56u) && ((unsigned)s < 56u);
        const float* bp = xb + (size_t)kb * HWX + r * 56 + s;
#pragma unroll
        for (int i = 0; i < 16; i++) bR[i] = ok ? __ldg(bp + i * (2 * HWX)) : 0.f;
#pragma unroll
        for (int i = 0; i < 16; i++) {
            sm[a_base + (i >> 1) * 128 + (i & 1)] = f2tf(aR[i]);
            int kloc = kb + 2 * i;
            sm[B_OFF + (kloc >> 3) * B_KSTRIDE + b_nt * B_NSTRIDE
               + (((b_nl << 2) | (kloc & 3)) << 1) + ((kloc >> 2) & 1)] = f2tf(bR[i]);
        }
    }
    __syncthreads();

    float acc[4][4][4];
#pragma unroll
    for (int i = 0; i < 4; i++)
#pragma unroll
        for (int j = 0; j < 4; j++)
#pragma unroll
            for (int r = 0; r < 4; r++) acc[i][j][r] = 0.f;

#pragma unroll 1
    for (int it = 0; it < NITER; it++) {
        const uint32_t abuf = (uint32_t)(it & 1) * A_BUF;
        const uint32_t bbuf = B_OFF + (uint32_t)(it & 1) * B_BUF;

        // ---- prefetch next chunk to regs ----
        if (it + 1 < NITER) {
            const int k0 = (it + 1) * BK;
#pragma unroll
            for (int i = 0; i < 16; i++) aR[i] = __ldg(&W[aoff[i] + k0 + lane_k]);
            const int t9 = k0 >> 8;
            const int kh = (t9 * 11) >> 5;      // t9/3
            const int kw = t9 - 3 * kh;
            const int r  = py + kh - 1;
            const int s  = px + kw - 1;
            const bool ok = ((unsigned)r < 56u) && ((unsigned)s < 56u);
            const float* bp = xb + (size_t)((k0 & 255) + kb) * HWX + r * 56 + s;
#pragma unroll
            for (int i = 0; i < 16; i++) bR[i] = ok ? __ldg(bp + i * (2 * HWX)) : 0.f;
        }

        // ---- compute on current buffer ----
#pragma unroll
        for (int ks = 0; ks < 4; ks++) {
            uint32_t af[4][4], bf[4][2];
#pragma unroll
            for (int j = 0; j < 4; j++) {
                uint4 v = *(const uint4*)&sm[abuf + ks * A_KSTRIDE
                                             + (wm * 4 + j) * 128 + lane * 4];
                af[j][0] = v.x; af[j][1] = v.y; af[j][2] = v.z; af[j][3] = v.w;
            }
#pragma unroll
            for (int j = 0; j < 4; j++) {
                uint2 v = *(const uint2*)&sm[bbuf + ks * B_KSTRIDE
                                             + (wn * 4 + j) * B_NSTRIDE + lane * 2];
                bf[j][0] = v.x; bf[j][1] = v.y;
            }
#pragma unroll
            for (int mi = 0; mi < 4; mi++)
#pragma unroll
                for (int nj = 0; nj < 4; nj++)
                    mma8(acc[mi][nj], af[mi], bf[nj]);
        }

        // ---- store next chunk into other buffer ----
        if (it + 1 < NITER) {
            const uint32_t na = (uint32_t)((it + 1) & 1) * A_BUF;
            const uint32_t nb = B_OFF + (uint32_t)((it + 1) & 1) * B_BUF;
#pragma unroll
            for (int i = 0; i < 16; i++) {
                sm[na + a_base + (i >> 1) * 128 + (i & 1)] = f2tf(aR[i]);
                int kloc = kb + 2 * i;
                sm[nb + (kloc >> 3) * B_KSTRIDE + b_nt * B_NSTRIDE
                   + (((b_nl << 2) | (kloc & 3)) << 1) + ((kloc >> 2) & 1)] = f2tf(bR[i]);
            }
            __syncthreads();
        }
    }

    // ---------------- epilogue ----------------
#pragma unroll
    for (int mi = 0; mi < 4; mi++) {
        const int row0 = wm * 64 + mi * 16 + (lane >> 2);
#pragma unroll
        for (int rp = 0; rp < 2; rp++) {
            const int m  = row0 + rp * 8;
            const int gi = mt * MT + m;
            if (gi >= active) continue;
            const int g  = g_sel[gi];
            const float mu = g_mul[g];
            const float bb = __ldg(&bias[g]);
#pragma unroll
            for (int nj = 0; nj < 4; nj++) {
                const int col = wn * 32 + nj * 8 + 2 * (lane & 3);
                const int pp  = nt * NT + col;
                const int n   = pp / HWX;
                const int rem = pp - n * HWX;
                float2 v;
                v.x = fmaf(mu, acc[mi][nj][rp * 2 + 0], bb);
                v.y = fmaf(mu, acc[mi][nj][rp * 2 + 1], bb);
                *(float2*)&out[((size_t)n * OUTC + g) * HWX + rem] = v;
            }
        }
    }
}

// ============================================================================
extern "C" void kernel_launch(void* const* d_in, const int* in_sizes, int n_in,
                              void* d_out, int out_size) {
    const float* x = nullptr;
    const float* W = nullptr;
    const float* bias = nullptr;
    const float* a = nullptr;
    for (int i = 0; i < n_in; i++) {
        if (in_sizes[i] == NIMG * INC * HWX)      x    = (const float*)d_in[i];
        else if (in_sizes[i] == OUTC * D_TOT)     W    = (const float*)d_in[i];
        else if (in_sizes[i] == OUTC)             bias = (const float*)d_in[i];
        else if (in_sizes[i] == D_TOT + 5)        a    = (const float*)d_in[i];
    }
    float* out = (float*)d_out;

    const int smem_bytes = SMEM_U32 * 4;   // 66816
    cudaFuncSetAttribute(conv_mma, cudaFuncAttributeMaxDynamicSharedMemorySize,
                         smem_bytes);

    hash_kernels<<<OUTC, 256>>>(W, a);
    max_rows<<<INC, 256>>>(x);
    build_route<<<1, 512>>>(a);
    fill_bias<<<(NPIX * (OUTC / 4)) / 256, 256>>>((float4*)out, bias);
    conv_mma<<<dim3(NPIX / NT, (OUTC + MT - 1) / MT), 256, smem_bytes>>>(x, W, bias, out);
}

// round 4
// speedup vs baseline: 7.2940x; 1.6054x over previous
#include <cuda_runtime.h>
#include <cuda_fp16.h>
#include <math.h>
#include <stdint.h>

#define D_TOT 2304
#define OUTC  512
#define INC   256
#define HWX   3136          // 56*56
#define NIMG  16
#define NPIX  (NIMG*HWX)    // 50176

#define BK    32
#define NITER (D_TOT/BK)    // 72
#define MT    128           // CTA M tile (channels)
#define NT    128           // CTA N tile (pixels)

// SMEM (u32 units): fragment-ordered packed-half2 tiles, double buffered.
// A: per kstep(16k) 8 mtiles * 128 u32 = 1024 (+8 pad); 2 ksteps/chunk
// B: per kstep 16 ntiles * 66 u32; 2 ksteps/chunk
#define A_KSTRIDE 1032
#define A_BUF     2064      // 2*1032
#define B_NSTRIDE 66
#define B_KSTRIDE 1056      // 16*66
#define B_BUF     2112      // 2*1056
#define B_OFF     4128      // 2*A_BUF
#define SMEM_U32  (B_OFF + 2*B_BUF)   // 8352 u32 = 33408 B

// scratch (device globals: no allocation allowed)
__device__ int   g_kidx[OUTC];
__device__ float g_maxrow[D_TOT];
__device__ float g_mul[OUTC];
__device__ int   g_sel[OUTC];
__device__ int   g_active;

// ============================ helpers ========================================
__device__ __forceinline__ uint32_t packh2(float lo, float hi) {
    __half2 h = __floats2half2_rn(lo, hi);
    return *reinterpret_cast<uint32_t*>(&h);
}
__device__ __forceinline__ void mma16(float* c, const uint32_t* a, const uint32_t* b) {
    asm volatile(
        "mma.sync.aligned.m16n8k16.row.col.f32.f16.f16.f32 "
        "{%0,%1,%2,%3}, {%4,%5,%6,%7}, {%8,%9}, {%0,%1,%2,%3};\n"
        : "+f"(c[0]), "+f"(c[1]), "+f"(c[2]), "+f"(c[3])
        : "r"(a[0]), "r"(a[1]), "r"(a[2]), "r"(a[3]), "r"(b[0]), "r"(b[1]));
}

// ============================ small kernels ==================================
__global__ void __launch_bounds__(256) hash_kernels(const float* __restrict__ W,
                                                    const float* __restrict__ a) {
    const int o   = blockIdx.x;
    const int tid = threadIdx.x;
    const float* w = W + (size_t)o * D_TOT;
    float dot = 0.f, n2 = 0.f;
    for (int i = tid; i < D_TOT; i += 256) {
        float v = w[i];
        dot += a[i] * v;
        n2  += v * v;
    }
    __shared__ float s1[256], s2[256];
    s1[tid] = dot; s2[tid] = n2;
    __syncthreads();
    for (int st = 128; st > 0; st >>= 1) {
        if (tid < st) { s1[tid] += s1[tid+st]; s2[tid] += s2[tid+st]; }
        __syncthreads();
    }
    if (tid == 0) {
        float acc = s1[0];
        float pw  = s2[0];
        acc += a[D_TOT+0] * pw; pw *= pw;
        acc += a[D_TOT+1] * pw; pw *= pw;
        acc += a[D_TOT+2] * pw; pw *= pw;
        acc += a[D_TOT+3] * pw; pw *= pw;
        acc += a[D_TOT+4] * pw;
        float h = floorf(acc);
        float r = fmodf(h, 16.f);
        if (r < 0.f) r += 16.f;
        g_kidx[o] = (int)r;
    }
}

__global__ void __launch_bounds__(256) max_rows(const float* __restrict__ x) {
    const int c   = blockIdx.x;
    const int tid = threadIdx.x;
    float m[9];
#pragma unroll
    for (int i = 0; i < 9; i++) m[i] = -1e30f;
    for (int t = tid; t < NIMG * HWX; t += 256) {
        int n = t / HWX;
        int i = t - n * HWX;
        int r = i / 56;
        int s = i - r * 56;
        float v = __ldg(&x[((size_t)n * INC + c) * HWX + i]);
        bool r0 = (r <= 54), r2 = (r >= 1), c0 = (s <= 54), c2 = (s >= 1);
        m[4] = fmaxf(m[4], v);
        if (r0) { m[1] = fmaxf(m[1], v); if (c0) m[0] = fmaxf(m[0], v); if (c2) m[2] = fmaxf(m[2], v); }
        if (c0) m[3] = fmaxf(m[3], v);
        if (c2) m[5] = fmaxf(m[5], v);
        if (r2) { m[7] = fmaxf(m[7], v); if (c0) m[6] = fmaxf(m[6], v); if (c2) m[8] = fmaxf(m[8], v); }
    }
    __shared__ float sred[256];
    for (int q = 0; q < 9; q++) {
        sred[tid] = m[q];
        __syncthreads();
        for (int st = 128; st > 0; st >>= 1) {
            if (tid < st) sred[tid] = fmaxf(sred[tid], sred[tid+st]);
            __syncthreads();
        }
        if (tid == 0) {
            float mv = sred[0];
            if (q != 4) mv = fmaxf(mv, 0.f);
            g_maxrow[q * INC + c] = mv;
        }
        __syncthreads();
    }
}

__global__ void __launch_bounds__(512) build_route(const float* __restrict__ a) {
    const int tid = threadIdx.x;
    __shared__ float red[512];

    float ss = 0.f;
    for (int i = tid; i < D_TOT; i += 512) { float v = g_maxrow[i]; ss += v * v; }
    red[tid] = ss; __syncthreads();
    for (int st = 256; st > 0; st >>= 1) { if (tid < st) red[tid] += red[tid+st]; __syncthreads(); }
    __shared__ float s_norm;
    if (tid == 0) s_norm = sqrtf(red[0]);
    __syncthreads();

    float dot = 0.f;
    for (int i = tid; i < D_TOT; i += 512) dot += a[i] * g_maxrow[i];
    red[tid] = dot; __syncthreads();
    for (int st = 256; st > 0; st >>= 1) { if (tid < st) red[tid] += red[tid+st]; __syncthreads(); }

    __shared__ int s_q, s_cnt, s_pos;
    if (tid == 0) {
        float hs = 0.5f * (a[D_TOT] + a[D_TOT+1] + a[D_TOT+2] + a[D_TOT+3] + a[D_TOT+4]);
        float acc = red[0] / s_norm + hs;
        float h = floorf(acc);
        float r = fmodf(h, 16.f);
        if (r < 0.f) r += 16.f;
        s_q = (int)r;
        s_cnt = 0; s_pos = 0;
    }
    __syncthreads();

    int match = (g_kidx[tid] == s_q) ? 1 : 0;
    if (match) atomicAdd(&s_cnt, 1);
    __syncthreads();
    int count = s_cnt;

    if (count > 0) {
        g_mul[tid] = match ? ((float)OUTC / (float)count) : 0.f;
        if (match) { int pp = atomicAdd(&s_pos, 1); g_sel[pp] = tid; }
        if (tid == 0) g_active = count;
    } else {
        g_mul[tid] = 1.f;
        g_sel[tid] = tid;
        if (tid == 0) g_active = OUTC;
    }
}

// 1568 blocks x 256 threads x 16 float4 = 6,422,528 float4
__global__ void __launch_bounds__(256) fill_bias(float4* __restrict__ out,
                                                 const float* __restrict__ bias) {
    if (g_active == OUTC) return;   // conv writes every channel in this case
    int i = blockIdx.x * 256 + threadIdx.x;
#pragma unroll
    for (int t = 0; t < 16; t++) {
        int o = (i / 784) & 511;
        float b = __ldg(&bias[o]);
        out[i] = make_float4(b, b, b, b);
        i += 1568 * 256;
    }
}

// ============================ tensor-core conv ===============================
// D[m,n] = sum_k A[m,k]*B[n,k]; A row m -> W[g_sel[...]], B row n -> im2col col.
// mma.sync m16n8k16 f16 (fp32 accum). 8 warps, warp tile 64x32.
__global__ void __launch_bounds__(256) conv_mma(const float* __restrict__ x,
                                                const float* __restrict__ W,
                                                const float* __restrict__ bias,
                                                float* __restrict__ out) {
    const int active = g_active;
    const int mt = blockIdx.y;
    if (mt * MT >= active) return;
    const int nt  = blockIdx.x;
    const int tid = threadIdx.x;
    const int wid  = tid >> 5;
    const int lane = tid & 31;
    const int wm = wid & 1;             // 0..1  (64 rows)
    const int wn = wid >> 1;            // 0..3  (32 cols)

    __shared__ uint32_t sm[SMEM_U32];

    // ---- A staging: thread (kp, rg): k-pair kp (k=2kp,2kp+1), rows rg+16i ----
    const int kp = tid & 15;            // 0..15
    const int rg = tid >> 4;            // 0..15
    uint32_t aoff[8];
#pragma unroll
    for (int i = 0; i < 8; i++) {
        int gi = mt * MT + rg + 16 * i;
        int g  = (gi < active) ? g_sel[gi] : 0;
        aoff[i] = (uint32_t)g * D_TOT;
    }
    // fragment: lane=(m&7)*4+((k&7)>>1); reg=(m>>3)|((k>>3)<<1); u32 packs (k,k+1)
    const int a_base = ((kp >> 3) ? A_KSTRIDE : 0)
                     + ((rg & 7) * 4 + (kp & 3)) * 4
                     + ((rg >> 3) & 1) + ((kp >> 2) & 1) * 2;

    // ---- B staging: thread (np, kh): pixel np, kstep kh, 8 k-pairs ----
    const int np = tid & 127;
    const int kh = tid >> 7;            // 0/1
    const int p  = nt * NT + np;
    const int pn = p / HWX;
    const int prem = p - pn * HWX;
    const int py = prem / 56;
    const int px = prem - py * 56;
    const float* xb = x + (size_t)pn * INC * HWX;
    const int b_base = B_OFF + kh * B_KSTRIDE + (np >> 3) * B_NSTRIDE + (np & 7) * 8;

    uint32_t aP[8], bP[8];

    // ---------------- prologue: stage chunk 0 into buf 0 ----------------
    {
#pragma unroll
        for (int i = 0; i < 8; i++) {
            float2 w2 = __ldg((const float2*)&W[aoff[i] + kp * 2]);
            aP[i] = packh2(w2.x, w2.y);
        }
        const int r = py - 1, s = px - 1;      // tap (0,0)
        const bool ok = ((unsigned)r < 56u) && ((unsigned)s < 56u);
        const float* bp = xb + (size_t)(kh * 16) * HWX + r * 56 + s;
#pragma unroll
        for (int j = 0; j < 8; j++) {
            float v0 = ok ? __ldg(bp + (2*j) * HWX)     : 0.f;
            float v1 = ok ? __ldg(bp + (2*j+1) * HWX)   : 0.f;
            bP[j] = packh2(v0, v1);
        }
#pragma unroll
        for (int i = 0; i < 8; i++) sm[a_base + i * 128] = aP[i];
#pragma unroll
        for (int j = 0; j < 8; j++) sm[b_base + (j & 3) * 2 + (j >> 2)] = bP[j];
    }
    __syncthreads();

    float acc[4][4][4];
#pragma unroll
    for (int i = 0; i < 4; i++)
#pragma unroll
        for (int j = 0; j < 4; j++)
#pragma unroll
            for (int r = 0; r < 4; r++) acc[i][j][r] = 0.f;

#pragma unroll 1
    for (int it = 0; it < NITER; it++) {
        const uint32_t abuf = (uint32_t)(it & 1) * A_BUF;
        const uint32_t bbuf = B_OFF + (uint32_t)(it & 1) * B_BUF;

        // ---- prefetch next chunk to regs (packed half2) ----
        if (it + 1 < NITER) {
            const int k0 = (it + 1) * BK;
#pragma unroll
            for (int i = 0; i < 8; i++) {
                float2 w2 = __ldg((const float2*)&W[aoff[i] + k0 + kp * 2]);
                aP[i] = packh2(w2.x, w2.y);
            }
            const int t9 = k0 >> 8;
            const int khh = (t9 * 11) >> 5;     // t9/3
            const int kww = t9 - 3 * khh;
            const int r  = py + khh - 1;
            const int s  = px + kww - 1;
            const bool ok = ((unsigned)r < 56u) && ((unsigned)s < 56u);
            const float* bp = xb + (size_t)((k0 & 255) + kh * 16) * HWX + r * 56 + s;
#pragma unroll
            for (int j = 0; j < 8; j++) {
                float v0 = ok ? __ldg(bp + (2*j) * HWX)   : 0.f;
                float v1 = ok ? __ldg(bp + (2*j+1) * HWX) : 0.f;
                bP[j] = packh2(v0, v1);
            }
        }

        // ---- compute on current buffer (2 ksteps of 16) ----
#pragma unroll
        for (int ks = 0; ks < 2; ks++) {
            uint32_t af[4][4], bf[4][2];
#pragma unroll
            for (int j = 0; j < 4; j++) {
                uint4 v = *(const uint4*)&sm[abuf + ks * A_KSTRIDE
                                             + (wm * 4 + j) * 128 + lane * 4];
                af[j][0] = v.x; af[j][1] = v.y; af[j][2] = v.z; af[j][3] = v.w;
            }
#pragma unroll
            for (int j = 0; j < 4; j++) {
                uint2 v = *(const uint2*)&sm[bbuf + ks * B_KSTRIDE
                                             + (wn * 4 + j) * B_NSTRIDE + lane * 2];
                bf[j][0] = v.x; bf[j][1] = v.y;
            }
#pragma unroll
            for (int mi = 0; mi < 4; mi++)
#pragma unroll
                for (int nj = 0; nj < 4; nj++)
                    mma16(acc[mi][nj], af[mi], bf[nj]);
        }

        // ---- store next chunk into other buffer ----
        if (it + 1 < NITER) {
            const uint32_t na = (uint32_t)((it + 1) & 1) * A_BUF;
            const uint32_t nb = (uint32_t)((it + 1) & 1) * B_BUF;
#pragma unroll
            for (int i = 0; i < 8; i++) sm[na + a_base + i * 128] = aP[i];
#pragma unroll
            for (int j = 0; j < 8; j++) sm[nb + b_base + (j & 3) * 2 + (j >> 2)] = bP[j];
            __syncthreads();
        }
    }

    // ---------------- epilogue ----------------
#pragma unroll
    for (int mi = 0; mi < 4; mi++) {
        const int row0 = wm * 64 + mi * 16 + (lane >> 2);
#pragma unroll
        for (int rp = 0; rp < 2; rp++) {
            const int m  = row0 + rp * 8;
            const int gi = mt * MT + m;
            if (gi >= active) continue;
            const int g  = g_sel[gi];
            const float mu = g_mul[g];
            const float bb = __ldg(&bias[g]);
#pragma unroll
            for (int nj = 0; nj < 4; nj++) {
                const int col = wn * 32 + nj * 8 + 2 * (lane & 3);
                const int pp  = nt * NT + col;
                const int n   = pp / HWX;
                const int rem = pp - n * HWX;
                float2 v;
                v.x = fmaf(mu, acc[mi][nj][rp * 2 + 0], bb);
                v.y = fmaf(mu, acc[mi][nj][rp * 2 + 1], bb);
                *(float2*)&out[((size_t)n * OUTC + g) * HWX + rem] = v;
            }
        }
    }
}

// ============================================================================
extern "C" void kernel_launch(void* const* d_in, const int* in_sizes, int n_in,
                              void* d_out, int out_size) {
    const float* x = nullptr;
    const float* W = nullptr;
    const float* bias = nullptr;
    const float* a = nullptr;
    for (int i = 0; i < n_in; i++) {
        if (in_sizes[i] == NIMG * INC * HWX)      x    = (const float*)d_in[i];
        else if (in_sizes[i] == OUTC * D_TOT)     W    = (const float*)d_in[i];
        else if (in_sizes[i] == OUTC)             bias = (const float*)d_in[i];
        else if (in_sizes[i] == D_TOT + 5)        a    = (const float*)d_in[i];
    }
    float* out = (float*)d_out;

    hash_kernels<<<OUTC, 256>>>(W, a);
    max_rows<<<INC, 256>>>(x);
    build_route<<<1, 512>>>(a);
    fill_bias<<<1568, 256>>>((float4*)out, bias);
    conv_mma<<<dim3(NPIX / NT, (OUTC + MT - 1) / MT), 256>>>(x, W, bias, out);
}